// round 16
// baseline (speedup 1.0000x reference)
#include <cuda_runtime.h>

#define BB 64
#define SS 1024
#define DD 16
#define TOK (BB * SS)
#define NP 66                 // Taylor pairs (a+b <= 10)

// Scratch (allocation-free rule: __device__ globals)
__device__ float2 g_q[TOK];              // q / 4
__device__ float4 g_kv[TOK];             // (k0,k1,v0,v1) f32
__device__ float2 g_ksum[TOK / 256];     // per-256-token-block k sums
__device__ float  g_M[128 * NP * 3];     // per half-batch moments (fact folded)
__device__ float  g_A[256];              // diag(g) @ (W1W2W3 + I)
__device__ float  g_csA[16];
__device__ float  g_bA[16];
__device__ float  g_O[256];              // diag(g) @ Wo
__device__ float  g_csO[16];
__device__ float  g_bO[16];

// ---------------------------------------------------------------------------
// Kernel 1: QKV projection (q pre-scaled by 1/4) + per-block k-sums.
// Last block folds the epilogue weights.
// ---------------------------------------------------------------------------
__global__ void __launch_bounds__(256)
qkv_precomp_kernel(const float* __restrict__ x,
                   const float* __restrict__ Wq, const float* __restrict__ bq,
                   const float* __restrict__ Wk, const float* __restrict__ bk,
                   const float* __restrict__ Wv, const float* __restrict__ bv,
                   const float* __restrict__ W1, const float* __restrict__ b1,
                   const float* __restrict__ W2, const float* __restrict__ b2,
                   const float* __restrict__ W3, const float* __restrict__ b3,
                   const float* __restrict__ ln_g, const float* __restrict__ ln_b,
                   const float* __restrict__ Wo, const float* __restrict__ bo)
{
    int tid = threadIdx.x;

    if (blockIdx.x == TOK / 256) {
        // ------- precompute folded epilogue weights -------
        __shared__ float s1[256], s2[256], s3[256], s12[256];
        __shared__ float sA[256], sAraw[256], sO[256];
        __shared__ float sbp[16], sbc[16], sg[16], sb[16];
        int r = tid >> 4, c = tid & 15;
        s1[tid] = W1[tid]; s2[tid] = W2[tid]; s3[tid] = W3[tid];
        if (tid < 16) { sg[tid] = ln_g[tid]; sb[tid] = ln_b[tid]; }
        __syncthreads();

        float acc = 0.f;
        #pragma unroll
        for (int k = 0; k < 16; k++) acc = fmaf(s1[r*16+k], s2[k*16+c], acc);
        s12[tid] = acc;
        if (tid < 16) {
            float t = b2[tid];
            #pragma unroll
            for (int k = 0; k < 16; k++) t = fmaf(b1[k], s2[k*16+tid], t);
            sbp[tid] = t;
        }
        __syncthreads();

        float w123 = 0.f;
        #pragma unroll
        for (int k = 0; k < 16; k++) w123 = fmaf(s12[r*16+k], s3[k*16+c], w123);
        float A = w123 + (r == c ? 1.0f : 0.0f);
        sAraw[tid] = A;
        sA[tid] = sg[r] * A;
        sO[tid] = sg[r] * Wo[tid];
        if (tid < 16) {
            float t = b3[tid];
            #pragma unroll
            for (int k = 0; k < 16; k++) t = fmaf(sbp[k], s3[k*16+tid], t);
            sbc[tid] = t;
        }
        __syncthreads();

        g_A[tid] = sA[tid];
        g_O[tid] = sO[tid];
        if (tid < 16) {
            float cs = 0.f, bb = sbc[tid];
            float cso = 0.f, bb2 = bo[tid];
            #pragma unroll
            for (int i = 0; i < 16; i++) {
                cs  += sA[i*16+tid];
                bb   = fmaf(sb[i], sAraw[i*16+tid], bb);
                cso += sO[i*16+tid];
                bb2  = fmaf(sb[i], Wo[i*16+tid], bb2);
            }
            g_csA[tid] = cs;  g_bA[tid] = bb;
            g_csO[tid] = cso; g_bO[tid] = bb2;
        }
        return;
    }

    // ------- QKV projection -------
    __shared__ float sw[102];
    __shared__ float2 swsum[8];
    if (tid < 32)        sw[tid] = Wq[tid];
    else if (tid < 64)   sw[tid] = Wk[tid - 32];
    else if (tid < 96)   sw[tid] = Wv[tid - 64];
    else if (tid < 98)   sw[tid] = bq[tid - 96];
    else if (tid < 100)  sw[tid] = bk[tid - 98];
    else if (tid < 102)  sw[tid] = bv[tid - 100];
    __syncthreads();

    int idx = blockIdx.x * 256 + tid;
    const float4* xp = reinterpret_cast<const float4*>(x + idx * DD);
    float xv[16];
    #pragma unroll
    for (int c4 = 0; c4 < 4; c4++) {
        float4 v = xp[c4];
        xv[4*c4+0] = v.x; xv[4*c4+1] = v.y; xv[4*c4+2] = v.z; xv[4*c4+3] = v.w;
    }

    float q0 = sw[96], q1 = sw[97];
    float k0 = sw[98], k1 = sw[99];
    float v0 = sw[100], v1 = sw[101];
    #pragma unroll
    for (int i = 0; i < 16; i++) {
        float xi = xv[i];
        q0 = fmaf(xi, sw[i*2+0],    q0);
        q1 = fmaf(xi, sw[i*2+1],    q1);
        k0 = fmaf(xi, sw[32+i*2+0], k0);
        k1 = fmaf(xi, sw[32+i*2+1], k1);
        v0 = fmaf(xi, sw[64+i*2+0], v0);
        v1 = fmaf(xi, sw[64+i*2+1], v1);
    }

    g_q[idx]  = make_float2(q0 * 0.25f, q1 * 0.25f);   // softmax scale folded
    g_kv[idx] = make_float4(k0, k1, v0, v1);

    // block k-sum for the batch mean
    float sk0 = k0, sk1 = k1;
    #pragma unroll
    for (int off = 16; off; off >>= 1) {
        sk0 += __shfl_down_sync(0xFFFFFFFFu, sk0, off);
        sk1 += __shfl_down_sync(0xFFFFFFFFu, sk1, off);
    }
    if ((tid & 31) == 0) swsum[tid >> 5] = make_float2(sk0, sk1);
    __syncthreads();
    if (tid == 0) {
        float a = 0.f, b = 0.f;
        #pragma unroll
        for (int i = 0; i < 8; i++) { a += swsum[i].x; b += swsum[i].y; }
        g_ksum[blockIdx.x] = make_float2(a, b);
    }
}

// ---------------------------------------------------------------------------
// Kernel 2: per-half-batch moments M_ab^(w) = sum_t d0^a d1^b * w_t,
// d = k - mu_batch, w in {1, v0, v1}, a+b <= 10 (66 pairs).
// Grid 128 (= batch*2 + half), block 288: thread = (pair p<66, chunk c<4).
// Factorials 1/(a! b!) folded into the stored moments.
// ---------------------------------------------------------------------------
__global__ void __launch_bounds__(288)
moments_kernel()
{
    __shared__ float4 skv[516];        // 512 tokens + pad every 128
    __shared__ float spart[264 * 3];

    int tid  = threadIdx.x;
    int b    = blockIdx.x >> 1;
    int half = blockIdx.x & 1;

    // batch mean of k
    float2 s0 = g_ksum[b*4+0], s1 = g_ksum[b*4+1];
    float2 s2 = g_ksum[b*4+2], s3 = g_ksum[b*4+3];
    float mu0 = (s0.x + s1.x + s2.x + s3.x) * (1.0f / 1024.0f);
    float mu1 = (s0.y + s1.y + s2.y + s3.y) * (1.0f / 1024.0f);

    int base = b * SS + half * 512;
    for (int i = tid; i < 512; i += 288)
        skv[i + (i >> 7)] = g_kv[base + i];
    __syncthreads();

    if (tid < 264) {
        int p = tid >> 2, c = tid & 3;
        // derive (a, b) from p: p = n(n+1)/2 + a
        int pp = p, n = 0;
        while (pp > n) { pp -= (n + 1); n++; }
        int ia = pp, ib = n - pp;

        float m1 = 0.f, mv0 = 0.f, mv1 = 0.f;
        int t0 = c * 128;
        for (int j = 0; j < 128; j++) {
            int t = t0 + j;
            float4 kv = skv[t + (t >> 7)];
            float d0 = kv.x - mu0, d1 = kv.y - mu1;
            float pw = 1.f;
            for (int i = 0; i < ia; i++) pw *= d0;
            for (int i = 0; i < ib; i++) pw *= d1;
            m1 += pw;
            mv0 = fmaf(pw, kv.z, mv0);
            mv1 = fmaf(pw, kv.w, mv1);
        }
        spart[tid*3+0] = m1; spart[tid*3+1] = mv0; spart[tid*3+2] = mv1;
    }
    __syncthreads();

    if (tid < NP) {
        int p = tid;
        int pp = p, n = 0;
        while (pp > n) { pp -= (n + 1); n++; }
        int ia = pp, ib = n - pp;
        const float FACT[11] = {1.f, 1.f, 2.f, 6.f, 24.f, 120.f, 720.f,
                                5040.f, 40320.f, 362880.f, 3628800.f};
        float invf = 1.0f / (FACT[ia] * FACT[ib]);

        float m1 = 0.f, mv0 = 0.f, mv1 = 0.f;
        #pragma unroll
        for (int c = 0; c < 4; c++) {
            int s = (p * 4 + c) * 3;
            m1 += spart[s+0]; mv0 += spart[s+1]; mv1 += spart[s+2];
        }
        int o = blockIdx.x * (NP * 3) + p * 3;
        g_M[o+0] = m1 * invf; g_M[o+1] = mv0 * invf; g_M[o+2] = mv1 * invf;
    }
}

// ---------------------------------------------------------------------------
// Kernel 3: epilogue. ctx from Taylor moments (no exp, no partials), then
// the LN-folded tail (measured-best form). 1 thread/token.
// ---------------------------------------------------------------------------
__global__ void __launch_bounds__(256)
epilogue_kernel(const float* __restrict__ x,
                const float* __restrict__ Wu, const float* __restrict__ bu,
                float* __restrict__ out)
{
    __shared__ __align__(16) float sA[256], sO[256], sWu[32];
    __shared__ float sbu[16], scsA[16], sbA[16], scsO[16], sbO[16];
    __shared__ float smM[NP * 3];

    int tid = threadIdx.x;
    int idx = blockIdx.x * 256 + tid;
    int b   = blockIdx.x >> 2;

    // Hoisted data loads
    float2 q = g_q[idx];
    const float4* xp = reinterpret_cast<const float4*>(x + idx * DD);
    float4 xv0 = xp[0], xv1 = xp[1], xv2 = xp[2], xv3 = xp[3];

    sA[tid] = g_A[tid]; sO[tid] = g_O[tid];
    if (tid < 32) sWu[tid] = Wu[tid];
    if (tid < 16) {
        sbu[tid] = bu[tid];
        scsA[tid] = g_csA[tid]; sbA[tid] = g_bA[tid];
        scsO[tid] = g_csO[tid]; sbO[tid] = g_bO[tid];
    }
    if (tid < NP * 3)
        smM[tid] = g_M[(b*2) * (NP*3) + tid] + g_M[(b*2+1) * (NP*3) + tid];
    __syncthreads();

    // powers of q'
    float P0[11], P1[11];
    P0[0] = 1.f; P1[0] = 1.f;
    #pragma unroll
    for (int i = 1; i <= 10; i++) { P0[i] = P0[i-1] * q.x; P1[i] = P1[i-1] * q.y; }

    // l, a0, a1 = sum over pairs of q0^a q1^b * M (factorials pre-folded)
    float l = 0.f, a0 = 0.f, a1 = 0.f;
    #pragma unroll
    for (int n = 0; n <= 10; n++) {
        #pragma unroll
        for (int a = 0; a <= n; a++) {
            const int p = n * (n + 1) / 2 + a;
            float term = P0[a] * P1[n - a];
            l  = fmaf(term, smM[p*3+0], l);
            a0 = fmaf(term, smM[p*3+1], a0);
            a1 = fmaf(term, smM[p*3+2], a1);
        }
    }
    float inv = 1.0f / l;
    float c0 = a0 * inv, c1 = a1 * inv;

    float xr[16] = {xv0.x, xv0.y, xv0.z, xv0.w, xv1.x, xv1.y, xv1.z, xv1.w,
                    xv2.x, xv2.y, xv2.z, xv2.w, xv3.x, xv3.y, xv3.z, xv3.w};

    // u = ctx @ Wu + bu + x
    float u[16];
    #pragma unroll
    for (int i = 0; i < 16; i++)
        u[i] = fmaf(c0, sWu[i], fmaf(c1, sWu[16 + i], sbu[i])) + xr[i];

    float su = 0.f, s2 = 0.f;
    #pragma unroll
    for (int i = 0; i < 16; i++) { su += u[i]; s2 = fmaf(u[i], u[i], s2); }
    float mu = su * (1.0f / 16.0f);
    float r  = rsqrtf(fmaf(-mu, mu, s2 * (1.0f / 16.0f)) + 1e-5f);

    float f[16];
    {
        float acc[16];
        #pragma unroll
        for (int j = 0; j < 16; j++) acc[j] = 0.f;
        #pragma unroll
        for (int i = 0; i < 16; i++) {
            float hv = u[i];
            const float4* wr = reinterpret_cast<const float4*>(sA + i * 16);
            #pragma unroll
            for (int j4 = 0; j4 < 4; j4++) {
                float4 w = wr[j4];
                acc[4*j4+0] = fmaf(hv, w.x, acc[4*j4+0]);
                acc[4*j4+1] = fmaf(hv, w.y, acc[4*j4+1]);
                acc[4*j4+2] = fmaf(hv, w.z, acc[4*j4+2]);
                acc[4*j4+3] = fmaf(hv, w.w, acc[4*j4+3]);
            }
        }
        #pragma unroll
        for (int j = 0; j < 16; j++)
            f[j] = fmaf(r, fmaf(-mu, scsA[j], acc[j]), sbA[j]);
    }

    float sf = 0.f, sf2 = 0.f;
    #pragma unroll
    for (int i = 0; i < 16; i++) { sf += f[i]; sf2 = fmaf(f[i], f[i], sf2); }
    float mu2 = sf * (1.0f / 16.0f);
    float r2  = rsqrtf(fmaf(-mu2, mu2, sf2 * (1.0f / 16.0f)) + 1e-5f);

    float o[16];
    {
        float acc[16];
        #pragma unroll
        for (int j = 0; j < 16; j++) acc[j] = 0.f;
        #pragma unroll
        for (int i = 0; i < 16; i++) {
            float hv = f[i];
            const float4* wr = reinterpret_cast<const float4*>(sO + i * 16);
            #pragma unroll
            for (int j4 = 0; j4 < 4; j4++) {
                float4 w = wr[j4];
                acc[4*j4+0] = fmaf(hv, w.x, acc[4*j4+0]);
                acc[4*j4+1] = fmaf(hv, w.y, acc[4*j4+1]);
                acc[4*j4+2] = fmaf(hv, w.z, acc[4*j4+2]);
                acc[4*j4+3] = fmaf(hv, w.w, acc[4*j4+3]);
            }
        }
        #pragma unroll
        for (int j = 0; j < 16; j++)
            o[j] = fmaf(r2, fmaf(-mu2, scsO[j], acc[j]), sbO[j]);
    }

    float4* op = reinterpret_cast<float4*>(out + idx * DD);
    #pragma unroll
    for (int c4 = 0; c4 < 4; c4++)
        op[c4] = make_float4(o[4*c4+0], o[4*c4+1], o[4*c4+2], o[4*c4+3]);
}

// ---------------------------------------------------------------------------
extern "C" void kernel_launch(void* const* d_in, const int* in_sizes, int n_in,
                              void* d_out, int out_size)
{
    const float* x    = (const float*)d_in[0];
    const float* Wq   = (const float*)d_in[1];
    const float* bq   = (const float*)d_in[2];
    const float* Wk   = (const float*)d_in[3];
    const float* bk   = (const float*)d_in[4];
    const float* Wv   = (const float*)d_in[5];
    const float* bv   = (const float*)d_in[6];
    const float* Wu   = (const float*)d_in[7];
    const float* bu   = (const float*)d_in[8];
    const float* ln_g = (const float*)d_in[9];
    const float* ln_b = (const float*)d_in[10];
    const float* W1   = (const float*)d_in[11];
    const float* b1   = (const float*)d_in[12];
    const float* W2   = (const float*)d_in[13];
    const float* b2   = (const float*)d_in[14];
    const float* W3   = (const float*)d_in[15];
    const float* b3   = (const float*)d_in[16];
    const float* Wo   = (const float*)d_in[17];
    const float* bo   = (const float*)d_in[18];
    float* out = (float*)d_out;

    qkv_precomp_kernel<<<TOK / 256 + 1, 256>>>(x, Wq, bq, Wk, bk, Wv, bv,
                                               W1, b1, W2, b2, W3, b3,
                                               ln_g, ln_b, Wo, bo);

    moments_kernel<<<128, 288>>>();

    epilogue_kernel<<<TOK / 256, 256>>>(x, Wu, bu, out);
}

// round 17
// speedup vs baseline: 3.1570x; 3.1570x over previous
#include <cuda_runtime.h>

#define BB 64
#define SS 1024
#define DD 16
#define TOK (BB * SS)
#define NP 66                 // Taylor pairs (a+b <= 10)

// Scratch (allocation-free rule: __device__ globals)
__device__ float2 g_q[TOK];              // q / 4
__device__ float4 g_kv[TOK];             // (k0,k1,v0,v1) f32
__device__ float2 g_ksum[TOK / 256];     // per-256-token-block k sums
__device__ float  g_M[128 * NP * 3];     // per half-batch moments (fact folded)
__device__ float  g_A[256];              // diag(g) @ (W1W2W3 + I)
__device__ float  g_csA[16];
__device__ float  g_bA[16];
__device__ float  g_O[256];              // diag(g) @ Wo
__device__ float  g_csO[16];
__device__ float  g_bO[16];

// ---------------------------------------------------------------------------
// Kernel 1: QKV projection (q pre-scaled by 1/4) + per-block k-sums.
// Last block folds the epilogue weights. (R16 form, unchanged.)
// ---------------------------------------------------------------------------
__global__ void __launch_bounds__(256)
qkv_precomp_kernel(const float* __restrict__ x,
                   const float* __restrict__ Wq, const float* __restrict__ bq,
                   const float* __restrict__ Wk, const float* __restrict__ bk,
                   const float* __restrict__ Wv, const float* __restrict__ bv,
                   const float* __restrict__ W1, const float* __restrict__ b1,
                   const float* __restrict__ W2, const float* __restrict__ b2,
                   const float* __restrict__ W3, const float* __restrict__ b3,
                   const float* __restrict__ ln_g, const float* __restrict__ ln_b,
                   const float* __restrict__ Wo, const float* __restrict__ bo)
{
    int tid = threadIdx.x;

    if (blockIdx.x == TOK / 256) {
        __shared__ float s1[256], s2[256], s3[256], s12[256];
        __shared__ float sA[256], sAraw[256], sO[256];
        __shared__ float sbp[16], sbc[16], sg[16], sb[16];
        int r = tid >> 4, c = tid & 15;
        s1[tid] = W1[tid]; s2[tid] = W2[tid]; s3[tid] = W3[tid];
        if (tid < 16) { sg[tid] = ln_g[tid]; sb[tid] = ln_b[tid]; }
        __syncthreads();

        float acc = 0.f;
        #pragma unroll
        for (int k = 0; k < 16; k++) acc = fmaf(s1[r*16+k], s2[k*16+c], acc);
        s12[tid] = acc;
        if (tid < 16) {
            float t = b2[tid];
            #pragma unroll
            for (int k = 0; k < 16; k++) t = fmaf(b1[k], s2[k*16+tid], t);
            sbp[tid] = t;
        }
        __syncthreads();

        float w123 = 0.f;
        #pragma unroll
        for (int k = 0; k < 16; k++) w123 = fmaf(s12[r*16+k], s3[k*16+c], w123);
        float A = w123 + (r == c ? 1.0f : 0.0f);
        sAraw[tid] = A;
        sA[tid] = sg[r] * A;
        sO[tid] = sg[r] * Wo[tid];
        if (tid < 16) {
            float t = b3[tid];
            #pragma unroll
            for (int k = 0; k < 16; k++) t = fmaf(sbp[k], s3[k*16+tid], t);
            sbc[tid] = t;
        }
        __syncthreads();

        g_A[tid] = sA[tid];
        g_O[tid] = sO[tid];
        if (tid < 16) {
            float cs = 0.f, bb = sbc[tid];
            float cso = 0.f, bb2 = bo[tid];
            #pragma unroll
            for (int i = 0; i < 16; i++) {
                cs  += sA[i*16+tid];
                bb   = fmaf(sb[i], sAraw[i*16+tid], bb);
                cso += sO[i*16+tid];
                bb2  = fmaf(sb[i], Wo[i*16+tid], bb2);
            }
            g_csA[tid] = cs;  g_bA[tid] = bb;
            g_csO[tid] = cso; g_bO[tid] = bb2;
        }
        return;
    }

    __shared__ float sw[102];
    __shared__ float2 swsum[8];
    if (tid < 32)        sw[tid] = Wq[tid];
    else if (tid < 64)   sw[tid] = Wk[tid - 32];
    else if (tid < 96)   sw[tid] = Wv[tid - 64];
    else if (tid < 98)   sw[tid] = bq[tid - 96];
    else if (tid < 100)  sw[tid] = bk[tid - 98];
    else if (tid < 102)  sw[tid] = bv[tid - 100];
    __syncthreads();

    int idx = blockIdx.x * 256 + tid;
    const float4* xp = reinterpret_cast<const float4*>(x + idx * DD);
    float xv[16];
    #pragma unroll
    for (int c4 = 0; c4 < 4; c4++) {
        float4 v = xp[c4];
        xv[4*c4+0] = v.x; xv[4*c4+1] = v.y; xv[4*c4+2] = v.z; xv[4*c4+3] = v.w;
    }

    float q0 = sw[96], q1 = sw[97];
    float k0 = sw[98], k1 = sw[99];
    float v0 = sw[100], v1 = sw[101];
    #pragma unroll
    for (int i = 0; i < 16; i++) {
        float xi = xv[i];
        q0 = fmaf(xi, sw[i*2+0],    q0);
        q1 = fmaf(xi, sw[i*2+1],    q1);
        k0 = fmaf(xi, sw[32+i*2+0], k0);
        k1 = fmaf(xi, sw[32+i*2+1], k1);
        v0 = fmaf(xi, sw[64+i*2+0], v0);
        v1 = fmaf(xi, sw[64+i*2+1], v1);
    }

    g_q[idx]  = make_float2(q0 * 0.25f, q1 * 0.25f);
    g_kv[idx] = make_float4(k0, k1, v0, v1);

    float sk0 = k0, sk1 = k1;
    #pragma unroll
    for (int off = 16; off; off >>= 1) {
        sk0 += __shfl_down_sync(0xFFFFFFFFu, sk0, off);
        sk1 += __shfl_down_sync(0xFFFFFFFFu, sk1, off);
    }
    if ((tid & 31) == 0) swsum[tid >> 5] = make_float2(sk0, sk1);
    __syncthreads();
    if (tid == 0) {
        float a = 0.f, b = 0.f;
        #pragma unroll
        for (int i = 0; i < 8; i++) { a += swsum[i].x; b += swsum[i].y; }
        g_ksum[blockIdx.x] = make_float2(a, b);
    }
}

// ---------------------------------------------------------------------------
// Kernel 2: per-half-batch moments. STRAIGHT-LINE power computation:
// predicated binary exponentiation (no dynamic loops, no branches) so the
// 128-token loop unrolls and pipelines.
// Grid 128 (= batch*2 + half), block 288: thread = (pair p<66, chunk c<4).
// ---------------------------------------------------------------------------
__global__ void __launch_bounds__(288)
moments_kernel()
{
    __shared__ float4 skv[516];        // 512 tokens + pad every 128
    __shared__ float spart[264 * 3];

    int tid  = threadIdx.x;
    int b    = blockIdx.x >> 1;
    int half = blockIdx.x & 1;

    float2 s0 = g_ksum[b*4+0], s1 = g_ksum[b*4+1];
    float2 s2 = g_ksum[b*4+2], s3 = g_ksum[b*4+3];
    float mu0 = (s0.x + s1.x + s2.x + s3.x) * (1.0f / 1024.0f);
    float mu1 = (s0.y + s1.y + s2.y + s3.y) * (1.0f / 1024.0f);

    int base = b * SS + half * 512;
    for (int i = tid; i < 512; i += 288)
        skv[i + (i >> 7)] = g_kv[base + i];
    __syncthreads();

    if (tid < 264) {
        int p = tid >> 2, c = tid & 3;
        // derive (a, b) from p: p = n(n+1)/2 + a  (runtime, outside hot loop)
        int pp = p, n = 0;
        while (pp > n) { pp -= (n + 1); n++; }
        int ia = pp, ib = n - pp;
        // loop-invariant selection masks
        bool a1s = ia & 1, a2s = ia & 2, a4s = ia & 4, a8s = ia & 8;
        bool b1s = ib & 1, b2s = ib & 2, b4s = ib & 4, b8s = ib & 8;

        float m1 = 0.f, mv0 = 0.f, mv1 = 0.f;
        int t0 = c * 128;
        #pragma unroll 8
        for (int j = 0; j < 128; j++) {
            int t = t0 + j;
            float4 kv = skv[t + (t >> 7)];
            float d0 = kv.x - mu0, d1 = kv.y - mu1;
            // pw = d0^ia * d1^ib via predicated square-and-multiply
            float pw = 1.f;
            float e = d0;
            pw = a1s ? pw * e : pw;  e *= e;
            pw = a2s ? pw * e : pw;  e *= e;
            pw = a4s ? pw * e : pw;  e *= e;
            pw = a8s ? pw * e : pw;
            e = d1;
            pw = b1s ? pw * e : pw;  e *= e;
            pw = b2s ? pw * e : pw;  e *= e;
            pw = b4s ? pw * e : pw;  e *= e;
            pw = b8s ? pw * e : pw;
            m1 += pw;
            mv0 = fmaf(pw, kv.z, mv0);
            mv1 = fmaf(pw, kv.w, mv1);
        }
        spart[tid*3+0] = m1; spart[tid*3+1] = mv0; spart[tid*3+2] = mv1;
    }
    __syncthreads();

    if (tid < NP) {
        int p = tid;
        int pp = p, n = 0;
        while (pp > n) { pp -= (n + 1); n++; }
        int ia = pp, ib = n - pp;
        const float FACT[11] = {1.f, 1.f, 2.f, 6.f, 24.f, 120.f, 720.f,
                                5040.f, 40320.f, 362880.f, 3628800.f};
        float invf = 1.0f / (FACT[ia] * FACT[ib]);

        float m1 = 0.f, mv0 = 0.f, mv1 = 0.f;
        #pragma unroll
        for (int c = 0; c < 4; c++) {
            int s = (p * 4 + c) * 3;
            m1 += spart[s+0]; mv0 += spart[s+1]; mv1 += spart[s+2];
        }
        int o = blockIdx.x * (NP * 3) + p * 3;
        g_M[o+0] = m1 * invf; g_M[o+1] = mv0 * invf; g_M[o+2] = mv1 * invf;
    }
}

// ---------------------------------------------------------------------------
// Kernel 3: epilogue. ctx from Taylor moments, then LN-folded tail.
// (R16 form, unchanged.)
// ---------------------------------------------------------------------------
__global__ void __launch_bounds__(256)
epilogue_kernel(const float* __restrict__ x,
                const float* __restrict__ Wu, const float* __restrict__ bu,
                float* __restrict__ out)
{
    __shared__ __align__(16) float sA[256], sO[256], sWu[32];
    __shared__ float sbu[16], scsA[16], sbA[16], scsO[16], sbO[16];
    __shared__ float smM[NP * 3];

    int tid = threadIdx.x;
    int idx = blockIdx.x * 256 + tid;
    int b   = blockIdx.x >> 2;

    float2 q = g_q[idx];
    const float4* xp = reinterpret_cast<const float4*>(x + idx * DD);
    float4 xv0 = xp[0], xv1 = xp[1], xv2 = xp[2], xv3 = xp[3];

    sA[tid] = g_A[tid]; sO[tid] = g_O[tid];
    if (tid < 32) sWu[tid] = Wu[tid];
    if (tid < 16) {
        sbu[tid] = bu[tid];
        scsA[tid] = g_csA[tid]; sbA[tid] = g_bA[tid];
        scsO[tid] = g_csO[tid]; sbO[tid] = g_bO[tid];
    }
    if (tid < NP * 3)
        smM[tid] = g_M[(b*2) * (NP*3) + tid] + g_M[(b*2+1) * (NP*3) + tid];
    __syncthreads();

    float P0[11], P1[11];
    P0[0] = 1.f; P1[0] = 1.f;
    #pragma unroll
    for (int i = 1; i <= 10; i++) { P0[i] = P0[i-1] * q.x; P1[i] = P1[i-1] * q.y; }

    float l = 0.f, a0 = 0.f, a1 = 0.f;
    #pragma unroll
    for (int n = 0; n <= 10; n++) {
        #pragma unroll
        for (int a = 0; a <= n; a++) {
            const int p = n * (n + 1) / 2 + a;
            float term = P0[a] * P1[n - a];
            l  = fmaf(term, smM[p*3+0], l);
            a0 = fmaf(term, smM[p*3+1], a0);
            a1 = fmaf(term, smM[p*3+2], a1);
        }
    }
    float inv = 1.0f / l;
    float c0 = a0 * inv, c1 = a1 * inv;

    float xr[16] = {xv0.x, xv0.y, xv0.z, xv0.w, xv1.x, xv1.y, xv1.z, xv1.w,
                    xv2.x, xv2.y, xv2.z, xv2.w, xv3.x, xv3.y, xv3.z, xv3.w};

    float u[16];
    #pragma unroll
    for (int i = 0; i < 16; i++)
        u[i] = fmaf(c0, sWu[i], fmaf(c1, sWu[16 + i], sbu[i])) + xr[i];

    float su = 0.f, s2 = 0.f;
    #pragma unroll
    for (int i = 0; i < 16; i++) { su += u[i]; s2 = fmaf(u[i], u[i], s2); }
    float mu = su * (1.0f / 16.0f);
    float r  = rsqrtf(fmaf(-mu, mu, s2 * (1.0f / 16.0f)) + 1e-5f);

    float f[16];
    {
        float acc[16];
        #pragma unroll
        for (int j = 0; j < 16; j++) acc[j] = 0.f;
        #pragma unroll
        for (int i = 0; i < 16; i++) {
            float hv = u[i];
            const float4* wr = reinterpret_cast<const float4*>(sA + i * 16);
            #pragma unroll
            for (int j4 = 0; j4 < 4; j4++) {
                float4 w = wr[j4];
                acc[4*j4+0] = fmaf(hv, w.x, acc[4*j4+0]);
                acc[4*j4+1] = fmaf(hv, w.y, acc[4*j4+1]);
                acc[4*j4+2] = fmaf(hv, w.z, acc[4*j4+2]);
                acc[4*j4+3] = fmaf(hv, w.w, acc[4*j4+3]);
            }
        }
        #pragma unroll
        for (int j = 0; j < 16; j++)
            f[j] = fmaf(r, fmaf(-mu, scsA[j], acc[j]), sbA[j]);
    }

    float sf = 0.f, sf2 = 0.f;
    #pragma unroll
    for (int i = 0; i < 16; i++) { sf += f[i]; sf2 = fmaf(f[i], f[i], sf2); }
    float mu2 = sf * (1.0f / 16.0f);
    float r2  = rsqrtf(fmaf(-mu2, mu2, sf2 * (1.0f / 16.0f)) + 1e-5f);

    float o[16];
    {
        float acc[16];
        #pragma unroll
        for (int j = 0; j < 16; j++) acc[j] = 0.f;
        #pragma unroll
        for (int i = 0; i < 16; i++) {
            float hv = f[i];
            const float4* wr = reinterpret_cast<const float4*>(sO + i * 16);
            #pragma unroll
            for (int j4 = 0; j4 < 4; j4++) {
                float4 w = wr[j4];
                acc[4*j4+0] = fmaf(hv, w.x, acc[4*j4+0]);
                acc[4*j4+1] = fmaf(hv, w.y, acc[4*j4+1]);
                acc[4*j4+2] = fmaf(hv, w.z, acc[4*j4+2]);
                acc[4*j4+3] = fmaf(hv, w.w, acc[4*j4+3]);
            }
        }
        #pragma unroll
        for (int j = 0; j < 16; j++)
            o[j] = fmaf(r2, fmaf(-mu2, scsO[j], acc[j]), sbO[j]);
    }

    float4* op = reinterpret_cast<float4*>(out + idx * DD);
    #pragma unroll
    for (int c4 = 0; c4 < 4; c4++)
        op[c4] = make_float4(o[4*c4+0], o[4*c4+1], o[4*c4+2], o[4*c4+3]);
}

// ---------------------------------------------------------------------------
extern "C" void kernel_launch(void* const* d_in, const int* in_sizes, int n_in,
                              void* d_out, int out_size)
{
    const float* x    = (const float*)d_in[0];
    const float* Wq   = (const float*)d_in[1];
    const float* bq   = (const float*)d_in[2];
    const float* Wk   = (const float*)d_in[3];
    const float* bk   = (const float*)d_in[4];
    const float* Wv   = (const float*)d_in[5];
    const float* bv   = (const float*)d_in[6];
    const float* Wu   = (const float*)d_in[7];
    const float* bu   = (const float*)d_in[8];
    const float* ln_g = (const float*)d_in[9];
    const float* ln_b = (const float*)d_in[10];
    const float* W1   = (const float*)d_in[11];
    const float* b1   = (const float*)d_in[12];
    const float* W2   = (const float*)d_in[13];
    const float* b2   = (const float*)d_in[14];
    const float* W3   = (const float*)d_in[15];
    const float* b3   = (const float*)d_in[16];
    const float* Wo   = (const float*)d_in[17];
    const float* bo   = (const float*)d_in[18];
    float* out = (float*)d_out;

    qkv_precomp_kernel<<<TOK / 256 + 1, 256>>>(x, Wq, bq, Wk, bk, Wv, bv,
                                               W1, b1, W2, b2, W3, b3,
                                               ln_g, ln_b, Wo, bo);

    moments_kernel<<<128, 288>>>();

    epilogue_kernel<<<TOK / 256, 256>>>(x, Wu, bu, out);
}